// round 8
// baseline (speedup 1.0000x reference)
#include <cuda_runtime.h>
#include <math.h>

#define NB 2
#define CH 128
#define NP 256
#define SS 240
#define MM 20
#define KXN 40
#define NPIX (SS*SS)
#define NPOS (NB*NPIX)

typedef unsigned long long ull;

// ---- scratch (device globals; no allocation allowed) ----
__device__ float  g_hA[NB*CH*NP*NP];
__device__ float  g_hB[NB*CH*NP*NP];
__device__ float2 g_Gy [NB*CH*NP*MM];
__device__ float2 g_Fm [NB*CH*KXN*MM];
__device__ float2 g_Fo [NB*CH*KXN*MM];
__device__ float2 g_Gy2[NB*CH*NP*MM];
__device__ float  g_feat[NPOS*CH];
__device__ float2 g_csy [NP*MM];     // (cos,sin)(2*pi*ky*y/256), y-major
__device__ float2 g_csx [NP*KXN];    // (cos,sin)(2*pi*kx*x/256), x-major
__device__ float2 g_csyT[MM*NP];     // ky-major copy

__device__ __forceinline__ float gelu_f(float v){
    return 0.5f*v*(1.0f+erff(v*0.70710678118654752f));
}

// ---- packed f32x2 helpers ----
__device__ __forceinline__ ull pk2(float lo, float hi){
    ull r; asm("mov.b64 %0, {%1,%2};" : "=l"(r) : "f"(lo), "f"(hi)); return r;
}
__device__ __forceinline__ ull dup2(float v){ return pk2(v,v); }
__device__ __forceinline__ ull fma2(ull a, ull b, ull c){
    ull d; asm("fma.rn.f32x2 %0, %1, %2, %3;" : "=l"(d) : "l"(a), "l"(b), "l"(c)); return d;
}
__device__ __forceinline__ float2 up2(ull v){
    float lo,hi; asm("mov.b64 {%0,%1}, %2;" : "=f"(lo), "=f"(hi) : "l"(v));
    return make_float2(lo,hi);
}

// ---- twiddle tables (exact: sincospif of integer/128) ----
__global__ void k_tables(){
    int i = blockIdx.x*blockDim.x + threadIdx.x;
    if (i < NP*MM){
        int y=i/MM, ky=i%MM; float s,c;
        sincospif((float)(ky*y)*(1.0f/128.0f), &s, &c);
        g_csy[i]=make_float2(c,s);
    } else if (i < NP*MM + NP*KXN){
        int j=i-NP*MM; int xx=j/KXN, kxi=j%KXN;
        int kx = (kxi<MM)? kxi : 236+(kxi-MM);
        float s,c; sincospif((float)(kx*xx)*(1.0f/128.0f), &s, &c);
        g_csx[j]=make_float2(c,s);
    } else if (i < 2*NP*MM + NP*KXN){
        int j=i-(NP*MM+NP*KXN); int ky=j/NP, y=j%NP;
        float s,c; sincospif((float)(ky*y)*(1.0f/128.0f), &s, &c);
        g_csyT[j]=make_float2(c,s);
    }
}

// ---- fc0 + grid channels, write padded (b,c,x,y) into g_hA ----
__global__ void k_fc0(const float* __restrict__ x, const float* __restrict__ w,
                      const float* __restrict__ b){
    __shared__ float ws[5][CH];
    __shared__ float bs[CH];
    int t=threadIdx.x;
    for(int i=t;i<5*CH;i+=256) ws[i/CH][i%CH]=w[i];
    for(int i=t;i<CH;i+=256) bs[i]=b[i];
    __syncthreads();
    int xr=blockIdx.x, bb=blockIdx.y, y=t;
    bool inside=(xr<SS)&&(y<SS);
    float v0=0.f,v1=0.f,v2=0.f,v3=0.f,v4=0.f;
    if(inside){
        const float* xp=x+(((size_t)bb*SS+xr)*SS+y)*3;
        v0=xp[0]; v1=xp[1]; v2=xp[2];
        v3=(float)xr*(1.0f/239.0f);
        v4=(float)y *(1.0f/239.0f);
    }
    float* op=g_hA+(((size_t)bb*CH)*NP+xr)*NP+y;
    for(int c=0;c<CH;c++){
        float a=0.f;
        if(inside){
            a=bs[c];
            a=fmaf(v0,ws[0][c],a); a=fmaf(v1,ws[1][c],a); a=fmaf(v2,ws[2][c],a);
            a=fmaf(v3,ws[3][c],a); a=fmaf(v4,ws[4][c],a);
        }
        op[(size_t)c*NP*NP]=a;
    }
}

// ---- forward y-DFT (packed re/im): h(row,y) -> Gy(row,ky) ----
__global__ void __launch_bounds__(320) k_dfty(int pp){
    __shared__ float hs[32*NP];
    const float* h = pp ? g_hB : g_hA;
    int t=threadIdx.x;
    size_t rowbase=(size_t)blockIdx.x*32;
    const float* hp=h+rowbase*NP;
    for(int i=t;i<32*NP;i+=320) hs[i]=hp[i];
    __syncthreads();
    int ky=t%MM, rl=t/MM;                 // rl 0..15, 2 rows each
    const float* h0=hs+(2*rl)*NP;
    const float* h1=h0+NP;
    ull a0=0ull, a1=0ull;                 // (sum u*c, sum u*s)
    const ull* cw=(const ull*)g_csy;
    #pragma unroll 4
    for(int y=0;y<NP;y++){
        ull w = cw[y*MM+ky];
        ull u0 = dup2(h0[y]);
        ull u1 = dup2(h1[y]);
        a0 = fma2(u0, w, a0);
        a1 = fma2(u1, w, a1);
    }
    float2 r0=up2(a0), r1=up2(a1);
    g_Gy[(rowbase+2*rl  )*MM+ky]=make_float2(r0.x,-r0.y);
    g_Gy[(rowbase+2*rl+1)*MM+ky]=make_float2(r1.x,-r1.y);
}

// ---- forward x-DFT (packed): Gy(x,ky) -> Fm(kxi,ky), one (b,c) per block ----
// 200 threads: (kxg 0..9, ky 0..19), each thread 4 kxi = {kxg, 10+kxg, 20+kxg, 30+kxg}
__global__ void __launch_bounds__(200) k_dftx(){
    __shared__ float2 gsh[NP*MM];              // 40KB
    int bc=blockIdx.x, t=threadIdx.x;
    const float2* gp=g_Gy+(size_t)bc*NP*MM;
    for(int i=t;i<NP*MM;i+=200) gsh[i]=gp[i];
    __syncthreads();
    int kxg=t%10, ky=t/10;
    ull accr[4], acci[4];
    #pragma unroll
    for(int j=0;j<4;j++){ accr[j]=0ull; acci[j]=0ull; }
    const ull* cwx=(const ull*)g_csx;
    #pragma unroll 2
    for(int xx=0;xx<NP;xx++){
        float2 g=gsh[xx*MM+ky];
        ull gnat=pk2(g.x,g.y);
        ull gswp=pk2(g.y,g.x);
        #pragma unroll
        for(int j=0;j<4;j++){
            ull w=cwx[xx*KXN + j*10 + kxg];    // natural (c,s)
            accr[j]=fma2(gnat,w,accr[j]);      // (gx*c, gy*s)
            acci[j]=fma2(gswp,w,acci[j]);      // (gy*c, gx*s)
        }
    }
    #pragma unroll
    for(int j=0;j<4;j++){
        float2 r=up2(accr[j]), im=up2(acci[j]);
        int kxi=j*10+kxg;
        g_Fm[((size_t)bc*KXN+kxi)*MM+ky]=make_float2(r.x+r.y, im.x-im.y);
    }
}

// ---- mode mixing (packed): Fo[b,o,p] = sum_i Fm[b,i,p]*W[i,o,p] ----
__global__ void __launch_bounds__(1024) k_mix(const float* __restrict__ w1,
                                              const float* __restrict__ w2, int l){
    __shared__ float2 fsh[2][CH][4];
    int kxi=blockIdx.x, myg=blockIdx.y, t=threadIdx.x;
    {
        int b=t>>9, rem=t&511, i=rem>>2, myl=rem&3;
        fsh[b][i][myl]=g_Fm[(((size_t)(b*CH+i))*KXN+kxi)*MM + myg*4+myl];
    }
    __syncthreads();
    int myl=t&3, b=(t>>2)&1, o=t>>3;
    int my=myg*4+myl;
    int mx=(kxi<MM)? kxi : (kxi-MM);
    const float2* wp=(const float2*)((kxi<MM)? w1 : w2);
    size_t base=(((size_t)l*CH*CH + o)*MM + mx)*MM + my;
    ull ar=0ull, ai=0ull;   // ar=(fx*wx, fy*wy): lo-hi ; ai=(fy*wx, fx*wy): lo+hi
    #pragma unroll 4
    for(int i=0;i<CH;i++){
        float2 wv=wp[base+(size_t)i*CH*MM*MM];
        float2 f=fsh[b][i][myl];
        ull w=pk2(wv.x,wv.y);
        ar=fma2(pk2(f.x,f.y), w, ar);
        ai=fma2(pk2(f.y,f.x), w, ai);
    }
    float2 r=up2(ar), im=up2(ai);
    g_Fo[(((size_t)(b*CH+o))*KXN+kxi)*MM+my]=make_float2(r.x-r.y, im.x+im.y);
}

// ---- inverse x-DFT (packed): Fo(kxi,ky) -> Gy2(x,ky), pre-scaled ----
__global__ void __launch_bounds__(512) k_idftx(){
    __shared__ float2 fsh[KXN*MM];
    int bo=blockIdx.x, t=threadIdx.x;
    const float2* fp=g_Fo+(size_t)bo*KXN*MM;
    for(int i=t;i<KXN*MM;i+=512) fsh[i]=fp[i];
    __syncthreads();
    int xx=t&255, kg=t>>8;                // kg 0..1, 10 ky each
    ull ar[10], ai[10];
    #pragma unroll
    for(int j=0;j<10;j++){ ar[j]=0ull; ai[j]=0ull; }
    for(int k=0;k<KXN;k++){
        float2 w=g_csx[xx*KXN+k];
        ull wr=pk2(w.x,-w.y);             // (c,-s)
        ull wi=pk2(w.y, w.x);             // (s, c)
        #pragma unroll
        for(int j=0;j<10;j++){
            float2 f=fsh[k*MM+kg*10+j];
            ull fn=pk2(f.x,f.y);
            ar[j]=fma2(fn,wr,ar[j]);      // (fx*c, -fy*s)  -> re = lo+hi
            ai[j]=fma2(fn,wi,ai[j]);      // (fx*s,  fy*c)  -> im = lo+hi
        }
    }
    float2* op=g_Gy2+((size_t)bo*NP+xx)*MM;
    #pragma unroll
    for(int j=0;j<10;j++){
        int ky=kg*10+j;
        float fk=((ky==0)?1.0f:2.0f)*(1.0f/65536.0f);
        float2 r=up2(ar[j]), im=up2(ai[j]);
        op[ky]=make_float2((r.x+r.y)*fk, (im.x+im.y)*fk);
    }
}

// ---- inverse y-DFT (packed, real part): write spectral term s into dst ----
__global__ void __launch_bounds__(256) k_idfty(int pp){
    __shared__ float2 rsh[32*MM];
    float* dst = pp ? g_hA : g_hB;
    int t=threadIdx.x;                    // y = t
    size_t rowbase=(size_t)blockIdx.x*32;
    const float2* gp=g_Gy2+rowbase*MM;
    for(int i=t;i<32*MM;i+=256) rsh[i]=gp[i];
    ull wv[MM];
    #pragma unroll
    for(int ky=0;ky<MM;ky++) wv[ky]=*(const ull*)&g_csyT[ky*NP+t];   // (c,s)
    __syncthreads();
    const ull* rp=(const ull*)rsh;
    for(int r=0;r<32;r++){
        ull acc=0ull;                     // (sum fr*c, sum fi*s)
        #pragma unroll
        for(int ky=0;ky<MM;ky++)
            acc=fma2(rp[r*MM+ky], wv[ky], acc);
        float2 p=up2(acc);
        dst[(rowbase+r)*NP+t]=p.x - p.y;  // fr*c - fi*s
    }
}

// ---- 1x1 conv GEMM (packed) + spectral + bias (+gelu) ----
__global__ void __launch_bounds__(256) k_lin(int pp, const float* __restrict__ ww,
                                             const float* __restrict__ wb, int l, int dogelu){
    const float* src = pp ? g_hB : g_hA;
    float*       dst = pp ? g_hA : g_hB;
    __shared__ float As2[16][128];        // duplicated weights [kk][2*o],[2*o+1]
    __shared__ float Bs[16][64];
    int t=threadIdx.x;
    int tile=blockIdx.x;
    int x=tile>>2, ybase=(tile&3)<<6;
    int obase=blockIdx.y<<6, bb=blockIdx.z;
    const float* W = ww + (size_t)l*CH*CH;
    int lo=t&63, kq=t>>6;
    const float* srow = src + (((size_t)bb*CH)*NP + x)*NP + ybase;
    ull acc2[4][2];                       // [oj][ypair]
    #pragma unroll
    for(int i=0;i<4;i++){ acc2[i][0]=0ull; acc2[i][1]=0ull; }
    int ty=t&15, to=t>>4;
    for(int c0=0;c0<CH;c0+=16){
        float4 w4 = *(const float4*)(W + (size_t)(obase+lo)*CH + c0 + kq*4);
        *(ull*)&As2[kq*4+0][2*lo]=dup2(w4.x);
        *(ull*)&As2[kq*4+1][2*lo]=dup2(w4.y);
        *(ull*)&As2[kq*4+2][2*lo]=dup2(w4.z);
        *(ull*)&As2[kq*4+3][2*lo]=dup2(w4.w);
        #pragma unroll
        for(int q=0;q<4;q++){
            int kk=kq*4+q;
            Bs[kk][lo]=srow[(size_t)(c0+kk)*NP*NP + lo];
        }
        __syncthreads();
        #pragma unroll
        for(int kk=0;kk<16;kk++){
            ulonglong2 a01=*(const ulonglong2*)&As2[kk][8*to];     // dup(o0),dup(o1)
            ulonglong2 a23=*(const ulonglong2*)&As2[kk][8*to+4];   // dup(o2),dup(o3)
            ulonglong2 bv =*(const ulonglong2*)&Bs[kk][4*ty];      // (y0,y1),(y2,y3)
            acc2[0][0]=fma2(a01.x,bv.x,acc2[0][0]);
            acc2[0][1]=fma2(a01.x,bv.y,acc2[0][1]);
            acc2[1][0]=fma2(a01.y,bv.x,acc2[1][0]);
            acc2[1][1]=fma2(a01.y,bv.y,acc2[1][1]);
            acc2[2][0]=fma2(a23.x,bv.x,acc2[2][0]);
            acc2[2][1]=fma2(a23.x,bv.y,acc2[2][1]);
            acc2[3][0]=fma2(a23.y,bv.x,acc2[3][0]);
            acc2[3][1]=fma2(a23.y,bv.y,acc2[3][1]);
        }
        __syncthreads();
    }
    #pragma unroll
    for(int oj=0;oj<4;oj++){
        int o=obase+to*4+oj;
        float bias=wb[l*CH+o];
        float* dp=dst+(((size_t)(bb*CH+o))*NP+x)*NP+ybase+ty*4;
        float4 s4=*(const float4*)dp;
        float2 p0=up2(acc2[oj][0]), p1=up2(acc2[oj][1]);
        float v0=p0.x+s4.x+bias;
        float v1=p0.y+s4.y+bias;
        float v2=p1.x+s4.z+bias;
        float v3=p1.y+s4.w+bias;
        if(dogelu){ v0=gelu_f(v0); v1=gelu_f(v1); v2=gelu_f(v2); v3=gelu_f(v3); }
        *(float4*)dp=make_float4(v0,v1,v2,v3);
    }
}

// ---- crop + fc1 (packed) + gelu -> g_feat ----
__global__ void __launch_bounds__(256) k_fc1(const float* __restrict__ w,
                                             const float* __restrict__ b){
    __shared__ float As[16][64];          // weights, natural over o
    __shared__ float Bs2[16][128];        // h, duplicated over p
    int t=threadIdx.x;
    int pbase=blockIdx.x*64, obase=blockIdx.y<<6;
    int lo=t&63, kq=t>>6;
    int p=pbase+lo;
    int bb=p/NPIX; int rem=p-bb*NPIX;
    int xr=rem/SS;  int yr=rem-xr*SS;
    size_t base=(size_t)bb*CH*NP*NP + (size_t)xr*NP + yr;
    ull acc2[4][2];                       // [pi][opair]
    #pragma unroll
    for(int i=0;i<4;i++){ acc2[i][0]=0ull; acc2[i][1]=0ull; }
    int tp=t&15, to=t>>4;
    for(int c0=0;c0<CH;c0+=16){
        #pragma unroll
        for(int q=0;q<4;q++){
            int kk=kq*4+q;
            As[kk][lo]=w[(size_t)(c0+kk)*CH + obase+lo];
            *(ull*)&Bs2[kk][2*lo]=dup2(g_hB[base + (size_t)(c0+kk)*NP*NP]);
        }
        __syncthreads();
        #pragma unroll
        for(int kk=0;kk<16;kk++){
            ulonglong2 b01=*(const ulonglong2*)&Bs2[kk][8*tp];     // dup(p0),dup(p1)
            ulonglong2 b23=*(const ulonglong2*)&Bs2[kk][8*tp+4];   // dup(p2),dup(p3)
            ulonglong2 av =*(const ulonglong2*)&As[kk][4*to];      // (o0,o1),(o2,o3)
            acc2[0][0]=fma2(b01.x,av.x,acc2[0][0]);
            acc2[0][1]=fma2(b01.x,av.y,acc2[0][1]);
            acc2[1][0]=fma2(b01.y,av.x,acc2[1][0]);
            acc2[1][1]=fma2(b01.y,av.y,acc2[1][1]);
            acc2[2][0]=fma2(b23.x,av.x,acc2[2][0]);
            acc2[2][1]=fma2(b23.x,av.y,acc2[2][1]);
            acc2[3][0]=fma2(b23.y,av.x,acc2[3][0]);
            acc2[3][1]=fma2(b23.y,av.y,acc2[3][1]);
        }
        __syncthreads();
    }
    #pragma unroll
    for(int pi=0;pi<4;pi++){
        float* fp=g_feat+(size_t)(pbase+tp*4+pi)*CH + obase+to*4;
        float2 p0=up2(acc2[pi][0]), p1=up2(acc2[pi][1]);
        float4 o4;
        o4.x=gelu_f(p0.x+b[obase+to*4+0]);
        o4.y=gelu_f(p0.y+b[obase+to*4+1]);
        o4.z=gelu_f(p1.x+b[obase+to*4+2]);
        o4.w=gelu_f(p1.y+b[obase+to*4+3]);
        *(float4*)fp=o4;
    }
}

// ---- 4 heads (packed GEMM1): gelu(feat@W1k+b1)@W2k + b2 -> out ----
__global__ void __launch_bounds__(256) k_heads(const float* __restrict__ w1,
                                               const float* __restrict__ b1,
                                               const float* __restrict__ w2,
                                               const float* __restrict__ b2,
                                               float* __restrict__ out){
    __shared__ float Fs2[32][128];        // feat, duplicated over p
    __shared__ float Ws[32][64];          // w1, natural over d
    __shared__ float red[64][17];
    int t=threadIdx.x;
    int pbase=blockIdx.x*64;
    int tp=t&15, td=t>>4;
    for(int k=0;k<4;k++){
        ull acc2[4][2];                   // [pi][dpair]
        #pragma unroll
        for(int i=0;i<4;i++){ acc2[i][0]=0ull; acc2[i][1]=0ull; }
        for(int c0=0;c0<CH;c0+=32){
            for(int i=t;i<2048;i+=256){
                int r=i>>6, cc=i&63;
                Ws[r][cc]=w1[(size_t)k*CH*64 + (size_t)(c0+r)*64 + cc];
            }
            for(int i=t;i<2048;i+=256){
                int c=i&31, pl=i>>5;
                *(ull*)&Fs2[c][2*pl]=dup2(g_feat[(size_t)(pbase+pl)*CH + c0 + c]);
            }
            __syncthreads();
            #pragma unroll 8
            for(int kk=0;kk<32;kk++){
                ulonglong2 f01=*(const ulonglong2*)&Fs2[kk][8*tp];
                ulonglong2 f23=*(const ulonglong2*)&Fs2[kk][8*tp+4];
                ulonglong2 av =*(const ulonglong2*)&Ws[kk][4*td];
                acc2[0][0]=fma2(f01.x,av.x,acc2[0][0]);
                acc2[0][1]=fma2(f01.x,av.y,acc2[0][1]);
                acc2[1][0]=fma2(f01.y,av.x,acc2[1][0]);
                acc2[1][1]=fma2(f01.y,av.y,acc2[1][1]);
                acc2[2][0]=fma2(f23.x,av.x,acc2[2][0]);
                acc2[2][1]=fma2(f23.x,av.y,acc2[2][1]);
                acc2[3][0]=fma2(f23.y,av.x,acc2[3][0]);
                acc2[3][1]=fma2(f23.y,av.y,acc2[3][1]);
            }
            __syncthreads();
        }
        #pragma unroll
        for(int pi=0;pi<4;pi++){
            float2 p0=up2(acc2[pi][0]), p1=up2(acc2[pi][1]);
            float aa[4]={p0.x,p0.y,p1.x,p1.y};
            float v=0.f;
            #pragma unroll
            for(int dj=0;dj<4;dj++){
                int d=td*4+dj;
                float h1=gelu_f(aa[dj]+b1[k*64+d]);
                v=fmaf(h1, w2[k*64+d], v);
            }
            red[tp*4+pi][td]=v;
        }
        __syncthreads();
        if(t<64){
            float v=b2[k];
            #pragma unroll
            for(int j=0;j<16;j++) v+=red[t][j];
            out[(size_t)k*NPOS + pbase + t]=v;
        }
        __syncthreads();
    }
}

extern "C" void kernel_launch(void* const* d_in, const int* in_sizes, int n_in,
                              void* d_out, int out_size){
    (void)in_sizes; (void)n_in; (void)out_size;
    const float* x     =(const float*)d_in[0];
    const float* fc0_w =(const float*)d_in[1];
    const float* fc0_b =(const float*)d_in[2];
    const float* sw1   =(const float*)d_in[3];
    const float* sw2   =(const float*)d_in[4];
    const float* w_w   =(const float*)d_in[5];
    const float* w_b   =(const float*)d_in[6];
    const float* fc1_w =(const float*)d_in[7];
    const float* fc1_b =(const float*)d_in[8];
    const float* h1w   =(const float*)d_in[9];
    const float* h1b   =(const float*)d_in[10];
    const float* h2w   =(const float*)d_in[11];
    const float* h2b   =(const float*)d_in[12];
    float* out=(float*)d_out;

    k_tables<<<80,256>>>();
    k_fc0<<<dim3(NP,NB),256>>>(x,fc0_w,fc0_b);
    for(int l=0;l<5;l++){
        int pp=l&1;
        k_dfty <<<NB*CH*NP/32,320>>>(pp);
        k_dftx <<<NB*CH,200>>>();
        k_mix  <<<dim3(KXN,5),1024>>>(sw1,sw2,l);
        k_idftx<<<NB*CH,512>>>();
        k_idfty<<<NB*CH*NP/32,256>>>(pp);
        k_lin  <<<dim3(NP*NP/64,2,NB),256>>>(pp,w_w,w_b,l,(l<4)?1:0);
    }
    k_fc1  <<<dim3(NPOS/64,2),256>>>(fc1_w,fc1_b);
    k_heads<<<NPOS/64,256>>>(h1w,h1b,h2w,h2b,out);
}

// round 9
// speedup vs baseline: 1.4430x; 1.4430x over previous
#include <cuda_runtime.h>
#include <math.h>

#define NB 2
#define CH 128
#define NP 256
#define SS 240
#define MM 20
#define KXN 40
#define NPIX (SS*SS)
#define NPOS (NB*NPIX)

// ---- scratch (device globals; no allocation allowed) ----
__device__ float  g_hA[NB*CH*NP*NP];
__device__ float  g_hB[NB*CH*NP*NP];
__device__ float2 g_Gy [NB*CH*NP*MM];
__device__ float2 g_Fm [NB*CH*KXN*MM];
__device__ float2 g_Fo [NB*CH*KXN*MM];
__device__ float2 g_Gy2[NB*CH*NP*MM];
__device__ float  g_feat[NPOS*CH];
__device__ float2 g_csy [NP*MM];     // (cos,sin)(2*pi*ky*y/256), y-major
__device__ float2 g_csx [NP*KXN];    // (cos,sin)(2*pi*kx*x/256), x-major
__device__ float2 g_csyT[MM*NP];     // ky-major copy

__device__ __forceinline__ float gelu_f(float v){
    return 0.5f*v*(1.0f+erff(v*0.70710678118654752f));
}

// ---- twiddle tables (exact: sincospif of integer/128) ----
__global__ void k_tables(){
    int i = blockIdx.x*blockDim.x + threadIdx.x;
    if (i < NP*MM){
        int y=i/MM, ky=i%MM; float s,c;
        sincospif((float)(ky*y)*(1.0f/128.0f), &s, &c);
        g_csy[i]=make_float2(c,s);
    } else if (i < NP*MM + NP*KXN){
        int j=i-NP*MM; int xx=j/KXN, kxi=j%KXN;
        int kx = (kxi<MM)? kxi : 236+(kxi-MM);
        float s,c; sincospif((float)(kx*xx)*(1.0f/128.0f), &s, &c);
        g_csx[j]=make_float2(c,s);
    } else if (i < 2*NP*MM + NP*KXN){
        int j=i-(NP*MM+NP*KXN); int ky=j/NP, y=j%NP;
        float s,c; sincospif((float)(ky*y)*(1.0f/128.0f), &s, &c);
        g_csyT[j]=make_float2(c,s);
    }
}

// ---- fc0 + grid channels, write padded (b,c,x,y) into g_hA ----
__global__ void k_fc0(const float* __restrict__ x, const float* __restrict__ w,
                      const float* __restrict__ b){
    __shared__ float ws[5][CH];
    __shared__ float bs[CH];
    int t=threadIdx.x;
    for(int i=t;i<5*CH;i+=256) ws[i/CH][i%CH]=w[i];
    for(int i=t;i<CH;i+=256) bs[i]=b[i];
    __syncthreads();
    int xr=blockIdx.x, bb=blockIdx.y, y=t;
    bool inside=(xr<SS)&&(y<SS);
    float v0=0.f,v1=0.f,v2=0.f,v3=0.f,v4=0.f;
    if(inside){
        const float* xp=x+(((size_t)bb*SS+xr)*SS+y)*3;
        v0=xp[0]; v1=xp[1]; v2=xp[2];
        v3=(float)xr*(1.0f/239.0f);
        v4=(float)y *(1.0f/239.0f);
    }
    float* op=g_hA+(((size_t)bb*CH)*NP+xr)*NP+y;
    for(int c=0;c<CH;c++){
        float a=0.f;
        if(inside){
            a=bs[c];
            a=fmaf(v0,ws[0][c],a); a=fmaf(v1,ws[1][c],a); a=fmaf(v2,ws[2][c],a);
            a=fmaf(v3,ws[3][c],a); a=fmaf(v4,ws[4][c],a);
        }
        op[(size_t)c*NP*NP]=a;
    }
}

// ---- forward y-DFT: h(row,y) -> Gy(row,ky), 32 rows/block, 2 rows/thread ----
__global__ void __launch_bounds__(320) k_dfty(int pp){
    __shared__ float hs[32*NP];
    const float* h = pp ? g_hB : g_hA;
    int t=threadIdx.x;
    size_t rowbase=(size_t)blockIdx.x*32;
    const float* hp=h+rowbase*NP;
    for(int i=t;i<32*NP;i+=320) hs[i]=hp[i];
    __syncthreads();
    int ky=t%MM, rl=t/MM;                 // rl 0..15, 2 rows each
    const float* h0=hs+(2*rl)*NP;
    const float* h1=h0+NP;
    float a0r=0.f,a0i=0.f,a1r=0.f,a1i=0.f;
    #pragma unroll 4
    for(int y=0;y<NP;y++){
        float2 w=g_csy[y*MM+ky];
        float u0=h0[y], u1=h1[y];
        a0r=fmaf(u0,w.x,a0r); a0i=fmaf(u0,w.y,a0i);
        a1r=fmaf(u1,w.x,a1r); a1i=fmaf(u1,w.y,a1i);
    }
    g_Gy[(rowbase+2*rl  )*MM+ky]=make_float2(a0r,-a0i);
    g_Gy[(rowbase+2*rl+1)*MM+ky]=make_float2(a1r,-a1i);
}

// ---- forward x-DFT: Gy(x,ky) -> Fm(kxi,ky), one (b,c) per block ----
__global__ void __launch_bounds__(800) k_dftx(){
    __shared__ float2 gsh[NP*MM];
    int bc=blockIdx.x, t=threadIdx.x;
    const float2* gp=g_Gy+(size_t)bc*NP*MM;
    for(int i=t;i<NP*MM;i+=800) gsh[i]=gp[i];
    __syncthreads();
    int kxi=t%KXN, ky=t/KXN;
    float ar=0.f, ai=0.f;
    #pragma unroll 4
    for(int xx=0;xx<NP;xx++){
        float2 w=g_csx[xx*KXN+kxi];
        float2 f=gsh[xx*MM+ky];
        ar += f.x*w.x + f.y*w.y;          // F = sum G * e^{-i th}
        ai += f.y*w.x - f.x*w.y;
    }
    g_Fm[((size_t)bc*KXN+kxi)*MM+ky]=make_float2(ar,ai);
}

// ---- mode mixing: Fo[b,o,p] = sum_i Fm[b,i,p]*W[i,o,p] ----
__global__ void __launch_bounds__(1024) k_mix(const float* __restrict__ w1,
                                              const float* __restrict__ w2, int l){
    __shared__ float2 fsh[2][CH][4];
    int kxi=blockIdx.x, myg=blockIdx.y, t=threadIdx.x;
    {
        int b=t>>9, rem=t&511, i=rem>>2, myl=rem&3;
        fsh[b][i][myl]=g_Fm[(((size_t)(b*CH+i))*KXN+kxi)*MM + myg*4+myl];
    }
    __syncthreads();
    int myl=t&3, b=(t>>2)&1, o=t>>3;
    int my=myg*4+myl;
    int mx=(kxi<MM)? kxi : (kxi-MM);
    const float2* wp=(const float2*)((kxi<MM)? w1 : w2);
    size_t base=(((size_t)l*CH*CH + o)*MM + mx)*MM + my;       // i=0 term
    float ar=0.f, ai=0.f;
    #pragma unroll 4
    for(int i=0;i<CH;i++){
        float2 wv=wp[base+(size_t)i*CH*MM*MM];
        float2 f=fsh[b][i][myl];
        ar += f.x*wv.x - f.y*wv.y;
        ai += f.x*wv.y + f.y*wv.x;
    }
    g_Fo[(((size_t)(b*CH+o))*KXN+kxi)*MM+my]=make_float2(ar,ai);
}

// ---- inverse x-DFT: Fo(kxi,ky) -> Gy2(x,ky), pre-scaled ----
__global__ void __launch_bounds__(512) k_idftx(){
    __shared__ float2 fsh[KXN*MM];
    int bo=blockIdx.x, t=threadIdx.x;
    const float2* fp=g_Fo+(size_t)bo*KXN*MM;
    for(int i=t;i<KXN*MM;i+=512) fsh[i]=fp[i];
    __syncthreads();
    int xx=t&255, kg=t>>8;               // kg 0..1, 10 ky each
    float ar[10], ai[10];
    #pragma unroll
    for(int j=0;j<10;j++){ ar[j]=0.f; ai[j]=0.f; }
    for(int k=0;k<KXN;k++){
        float2 w=g_csx[xx*KXN+k];
        #pragma unroll
        for(int j=0;j<10;j++){
            float2 f=fsh[k*MM+kg*10+j];
            ar[j] += f.x*w.x - f.y*w.y;  // G2 = sum F * e^{+i th}
            ai[j] += f.x*w.y + f.y*w.x;
        }
    }
    float2* op=g_Gy2+((size_t)bo*NP+xx)*MM;
    #pragma unroll
    for(int j=0;j<10;j++){
        int ky=kg*10+j;
        float fk=((ky==0)?1.0f:2.0f)*(1.0f/65536.0f);
        op[ky]=make_float2(ar[j]*fk, ai[j]*fk);
    }
}

// ---- inverse y-DFT (real part): write spectral term s into dst ----
__global__ void __launch_bounds__(256) k_idfty(int pp){
    __shared__ float2 rsh[32*MM];
    float* dst = pp ? g_hA : g_hB;
    int t=threadIdx.x;
    size_t rowbase=(size_t)blockIdx.x*32;
    const float2* gp=g_Gy2+rowbase*MM;
    for(int i=t;i<32*MM;i+=256) rsh[i]=gp[i];
    float cy[MM], sy[MM];
    #pragma unroll
    for(int ky=0;ky<MM;ky++){ float2 w=g_csyT[ky*NP+t]; cy[ky]=w.x; sy[ky]=w.y; }
    __syncthreads();
    for(int r=0;r<32;r++){
        float a=0.f;
        #pragma unroll
        for(int ky=0;ky<MM;ky++){
            float2 f=rsh[r*MM+ky];
            a=fmaf(f.x,cy[ky],a);
            a=fmaf(-f.y,sy[ky],a);
        }
        dst[(rowbase+r)*NP+t]=a;
    }
}

// ---- 1x1 conv GEMM (128x128 tile, 8x8/thread) + spectral + bias (+gelu) ----
// grid.x = 512 (x 0..255, yhalf 0..1), grid.z = NB; 256 threads
__global__ void __launch_bounds__(256) k_lin(int pp, const float* __restrict__ ww,
                                             const float* __restrict__ wb, int l, int dogelu){
    const float* src = pp ? g_hB : g_hA;
    float*       dst = pp ? g_hA : g_hB;
    __shared__ float As[16][128];         // [k][o]
    __shared__ float Bs[16][128];         // [k][y]
    int t=threadIdx.x;
    int x=blockIdx.x>>1, ybase=(blockIdx.x&1)<<7, bb=blockIdx.z;
    const float* W = ww + (size_t)l*CH*CH;
    int lo=t&127, half=t>>7;              // As load indices
    int by=(t&31)*4, bk=t>>5;             // Bs load indices (bk 0..7)
    const float* srow = src + (((size_t)bb*CH)*NP + x)*NP + ybase;
    float acc[8][8];
    #pragma unroll
    for(int i=0;i<8;i++)
        #pragma unroll
        for(int j=0;j<8;j++) acc[i][j]=0.f;
    int ty=t&15, to=t>>4;
    for(int c0=0;c0<CH;c0+=16){
        float4 wa=*(const float4*)(W + (size_t)lo*CH + c0 + half*8);
        float4 wc=*(const float4*)(W + (size_t)lo*CH + c0 + half*8 + 4);
        As[half*8+0][lo]=wa.x; As[half*8+1][lo]=wa.y;
        As[half*8+2][lo]=wa.z; As[half*8+3][lo]=wa.w;
        As[half*8+4][lo]=wc.x; As[half*8+5][lo]=wc.y;
        As[half*8+6][lo]=wc.z; As[half*8+7][lo]=wc.w;
        *(float4*)&Bs[bk  ][by]=*(const float4*)(srow + (size_t)(c0+bk  )*NP*NP + by);
        *(float4*)&Bs[bk+8][by]=*(const float4*)(srow + (size_t)(c0+bk+8)*NP*NP + by);
        __syncthreads();
        #pragma unroll
        for(int kk=0;kk<16;kk++){
            float4 a0=*(const float4*)&As[kk][to*8];
            float4 a1=*(const float4*)&As[kk][to*8+4];
            float4 b0=*(const float4*)&Bs[kk][ty*8];
            float4 b1=*(const float4*)&Bs[kk][ty*8+4];
            float av[8]={a0.x,a0.y,a0.z,a0.w,a1.x,a1.y,a1.z,a1.w};
            float bv[8]={b0.x,b0.y,b0.z,b0.w,b1.x,b1.y,b1.z,b1.w};
            #pragma unroll
            for(int oj=0;oj<8;oj++)
                #pragma unroll
                for(int yj=0;yj<8;yj++)
                    acc[oj][yj]=fmaf(av[oj],bv[yj],acc[oj][yj]);
        }
        __syncthreads();
    }
    #pragma unroll
    for(int oj=0;oj<8;oj++){
        int o=to*8+oj;
        float bias=wb[l*CH+o];
        float* dp=dst+(((size_t)(bb*CH+o))*NP+x)*NP+ybase+ty*8;
        float4 s0=*(const float4*)dp;
        float4 s1=*(const float4*)(dp+4);
        float v[8];
        v[0]=acc[oj][0]+s0.x+bias; v[1]=acc[oj][1]+s0.y+bias;
        v[2]=acc[oj][2]+s0.z+bias; v[3]=acc[oj][3]+s0.w+bias;
        v[4]=acc[oj][4]+s1.x+bias; v[5]=acc[oj][5]+s1.y+bias;
        v[6]=acc[oj][6]+s1.z+bias; v[7]=acc[oj][7]+s1.w+bias;
        if(dogelu){
            #pragma unroll
            for(int j=0;j<8;j++) v[j]=gelu_f(v[j]);
        }
        *(float4*)dp    =make_float4(v[0],v[1],v[2],v[3]);
        *(float4*)(dp+4)=make_float4(v[4],v[5],v[6],v[7]);
    }
}

// ---- crop + fc1 + gelu -> g_feat (p-major, c contiguous) ----
__global__ void __launch_bounds__(256) k_fc1(const float* __restrict__ w,
                                             const float* __restrict__ b){
    __shared__ float As[16][64];
    __shared__ float Bs[16][64];
    int t=threadIdx.x;
    int pbase=blockIdx.x*64, obase=blockIdx.y<<6;
    int lo=t&63, kq=t>>6;
    int p=pbase+lo;
    int bb=p/NPIX; int rem=p-bb*NPIX;
    int xr=rem/SS;  int yr=rem-xr*SS;
    size_t base=(size_t)bb*CH*NP*NP + (size_t)xr*NP + yr;
    float acc[4][4];                      // [pi][oj]
    #pragma unroll
    for(int i=0;i<4;i++){ acc[i][0]=0.f; acc[i][1]=0.f; acc[i][2]=0.f; acc[i][3]=0.f; }
    int tp=t&15, to=t>>4;
    for(int c0=0;c0<CH;c0+=16){
        #pragma unroll
        for(int q=0;q<4;q++){
            int kk=kq*4+q;
            As[kk][lo]=w[(size_t)(c0+kk)*CH + obase+lo];
            Bs[kk][lo]=g_hB[base + (size_t)(c0+kk)*NP*NP];
        }
        __syncthreads();
        #pragma unroll
        for(int kk=0;kk<16;kk++){
            float4 a =*(const float4*)&As[kk][to*4];
            float4 bv=*(const float4*)&Bs[kk][tp*4];
            float av[4]={a.x,a.y,a.z,a.w};
            float bvv[4]={bv.x,bv.y,bv.z,bv.w};
            #pragma unroll
            for(int pi=0;pi<4;pi++)
                #pragma unroll
                for(int oj=0;oj<4;oj++)
                    acc[pi][oj]=fmaf(bvv[pi],av[oj],acc[pi][oj]);
        }
        __syncthreads();
    }
    #pragma unroll
    for(int pi=0;pi<4;pi++){
        float* fp=g_feat+(size_t)(pbase+tp*4+pi)*CH + obase+to*4;
        float4 o4;
        o4.x=gelu_f(acc[pi][0]+b[obase+to*4+0]);
        o4.y=gelu_f(acc[pi][1]+b[obase+to*4+1]);
        o4.z=gelu_f(acc[pi][2]+b[obase+to*4+2]);
        o4.w=gelu_f(acc[pi][3]+b[obase+to*4+3]);
        *(float4*)fp=o4;
    }
}

// ---- 4 heads: gelu(feat@W1k+b1)@W2k + b2 -> out ----
__global__ void __launch_bounds__(256) k_heads(const float* __restrict__ w1,
                                               const float* __restrict__ b1,
                                               const float* __restrict__ w2,
                                               const float* __restrict__ b2,
                                               float* __restrict__ out){
    __shared__ float Fs[32][65];
    __shared__ float Ws[32][64];
    __shared__ float red[64][17];
    int t=threadIdx.x;
    int pbase=blockIdx.x*64;
    int tp=t&15, td=t>>4;
    for(int k=0;k<4;k++){
        float acc[4][4];                  // [pi][dj]
        #pragma unroll
        for(int i=0;i<4;i++){ acc[i][0]=0.f; acc[i][1]=0.f; acc[i][2]=0.f; acc[i][3]=0.f; }
        for(int c0=0;c0<CH;c0+=32){
            for(int i=t;i<2048;i+=256){
                int r=i>>6, cc=i&63;
                Ws[r][cc]=w1[(size_t)k*CH*64 + (size_t)(c0+r)*64 + cc];
            }
            for(int i=t;i<2048;i+=256){
                int c=i&31, pl=i>>5;
                Fs[c][pl]=g_feat[(size_t)(pbase+pl)*CH + c0 + c];
            }
            __syncthreads();
            #pragma unroll 8
            for(int kk=0;kk<32;kk++){
                float4 a=*(const float4*)&Ws[kk][td*4];
                float av[4]={a.x,a.y,a.z,a.w};
                float f0=Fs[kk][tp*4+0], f1=Fs[kk][tp*4+1];
                float f2=Fs[kk][tp*4+2], f3=Fs[kk][tp*4+3];
                #pragma unroll
                for(int dj=0;dj<4;dj++){
                    acc[0][dj]=fmaf(f0,av[dj],acc[0][dj]);
                    acc[1][dj]=fmaf(f1,av[dj],acc[1][dj]);
                    acc[2][dj]=fmaf(f2,av[dj],acc[2][dj]);
                    acc[3][dj]=fmaf(f3,av[dj],acc[3][dj]);
                }
            }
            __syncthreads();
        }
        #pragma unroll
        for(int pi=0;pi<4;pi++){
            float v=0.f;
            #pragma unroll
            for(int dj=0;dj<4;dj++){
                int d=td*4+dj;
                float h1=gelu_f(acc[pi][dj]+b1[k*64+d]);
                v=fmaf(h1, w2[k*64+d], v);
            }
            red[tp*4+pi][td]=v;
        }
        __syncthreads();
        if(t<64){
            float v=b2[k];
            #pragma unroll
            for(int j=0;j<16;j++) v+=red[t][j];
            out[(size_t)k*NPOS + pbase + t]=v;
        }
        __syncthreads();
    }
}

extern "C" void kernel_launch(void* const* d_in, const int* in_sizes, int n_in,
                              void* d_out, int out_size){
    (void)in_sizes; (void)n_in; (void)out_size;
    const float* x     =(const float*)d_in[0];
    const float* fc0_w =(const float*)d_in[1];
    const float* fc0_b =(const float*)d_in[2];
    const float* sw1   =(const float*)d_in[3];
    const float* sw2   =(const float*)d_in[4];
    const float* w_w   =(const float*)d_in[5];
    const float* w_b   =(const float*)d_in[6];
    const float* fc1_w =(const float*)d_in[7];
    const float* fc1_b =(const float*)d_in[8];
    const float* h1w   =(const float*)d_in[9];
    const float* h1b   =(const float*)d_in[10];
    const float* h2w   =(const float*)d_in[11];
    const float* h2b   =(const float*)d_in[12];
    float* out=(float*)d_out;

    k_tables<<<80,256>>>();
    k_fc0<<<dim3(NP,NB),256>>>(x,fc0_w,fc0_b);
    for(int l=0;l<5;l++){
        int pp=l&1;
        k_dfty <<<NB*CH*NP/32,320>>>(pp);
        k_dftx <<<NB*CH,800>>>();
        k_mix  <<<dim3(KXN,5),1024>>>(sw1,sw2,l);
        k_idftx<<<NB*CH,512>>>();
        k_idfty<<<NB*CH*NP/32,256>>>(pp);
        k_lin  <<<dim3(512,1,NB),256>>>(pp,w_w,w_b,l,(l<4)?1:0);
    }
    k_fc1  <<<dim3(NPOS/64,2),256>>>(fc1_w,fc1_b);
    k_heads<<<NPOS/64,256>>>(h1w,h1b,h2w,h2b,out);
}